// round 4
// baseline (speedup 1.0000x reference)
#include <cuda_runtime.h>
#include <cuda_bf16.h>
#include <cstdint>

// Problem constants
#define NTOK 8192
#define DD   128
#define HH   16
#define DH   2048   // DD*HH

typedef __nv_bfloat16 bf16;

// ---------------------------------------------------------------------------
// Device scratch (no cudaMalloc allowed).
// ---------------------------------------------------------------------------
__device__ float g_Qp[(size_t)NTOK * DH];      // fp32 projections (attention input)
__device__ float g_Kp[(size_t)NTOK * DH];
__device__ float g_Vp[(size_t)NTOK * DH];

__device__ bf16  g_Aq[(size_t)NTOK * 3 * DD];  // packed [hi|lo|hi] inputs, K=384
__device__ bf16  g_Ak[(size_t)NTOK * 3 * DD];
__device__ bf16  g_Av[(size_t)NTOK * 3 * DD];
__device__ bf16  g_Bq[(size_t)3 * DD * DH];    // packed [hi;hi;lo] weights
__device__ bf16  g_Bk[(size_t)3 * DD * DH];
__device__ bf16  g_Bv[(size_t)3 * DD * DH];
__device__ bf16  g_Bo[(size_t)3 * DH * DD];    // Wo packed, K2=6144, N=128
__device__ bf16  g_Obf[(size_t)NTOK * 3 * DH]; // attention out, packed hi|lo|hi

// ---------------------------------------------------------------------------
// PTX helpers
// ---------------------------------------------------------------------------
__device__ __forceinline__ uint32_t smem_u32(const void* p) {
    return (uint32_t)__cvta_generic_to_shared(p);
}
__device__ __forceinline__ void ldm_x4(uint32_t& r0, uint32_t& r1, uint32_t& r2,
                                       uint32_t& r3, uint32_t addr) {
    asm volatile("ldmatrix.sync.aligned.m8n8.x4.shared.b16 {%0,%1,%2,%3}, [%4];\n"
                 : "=r"(r0), "=r"(r1), "=r"(r2), "=r"(r3) : "r"(addr));
}
__device__ __forceinline__ void ldm_x2_t(uint32_t& r0, uint32_t& r1, uint32_t addr) {
    asm volatile("ldmatrix.sync.aligned.m8n8.x2.trans.shared.b16 {%0,%1}, [%2];\n"
                 : "=r"(r0), "=r"(r1) : "r"(addr));
}
__device__ __forceinline__ void mma_bf16(float c[4], const uint32_t a[4],
                                         uint32_t b0, uint32_t b1) {
    asm volatile(
        "mma.sync.aligned.m16n8k16.row.col.f32.bf16.bf16.f32 "
        "{%0,%1,%2,%3}, {%4,%5,%6,%7}, {%8,%9}, {%0,%1,%2,%3};\n"
        : "+f"(c[0]), "+f"(c[1]), "+f"(c[2]), "+f"(c[3])
        : "r"(a[0]), "r"(a[1]), "r"(a[2]), "r"(a[3]), "r"(b0), "r"(b1));
}
__device__ __forceinline__ void cp_async16(void* dst, const void* src) {
    asm volatile("cp.async.cg.shared.global [%0], [%1], 16;\n"
                 :: "r"(smem_u32(dst)), "l"(src));
}
__device__ __forceinline__ void cp_commit() {
    asm volatile("cp.async.commit_group;\n");
}
template<int N>
__device__ __forceinline__ void cp_wait() {
    asm volatile("cp.async.wait_group %0;\n" :: "n"(N));
}

// split a float pair into bf16 (hi, lo) pairs
__device__ __forceinline__ void split2(float a, float b,
                                       __nv_bfloat162& hv, __nv_bfloat162& lv) {
    bf16 h0 = __float2bfloat16(a), h1 = __float2bfloat16(b);
    hv = __halves2bfloat162(h0, h1);
    lv = __halves2bfloat162(__float2bfloat16(a - __bfloat162float(h0)),
                            __float2bfloat16(b - __bfloat162float(h1)));
}

// ---------------------------------------------------------------------------
// Unified pack kernel.  blockIdx.y selects tensor:
//   0..2 : A-pack (q,k,v)   M=NTOK, K=DD      -> [hi | lo | hi] along K
//   3..5 : B-pack (Wq,Wk,Wv) K=DD,  N=DH      -> [hi ; hi ; lo] along K
//   6    : B-pack (Wo)       K=DH,  N=DD
// ---------------------------------------------------------------------------
__global__ void pack_all_kernel(const float* __restrict__ q, const float* __restrict__ k,
                                const float* __restrict__ v, const float* __restrict__ Wq,
                                const float* __restrict__ Wk, const float* __restrict__ Wv,
                                const float* __restrict__ Wo,
                                bf16* __restrict__ Aq, bf16* __restrict__ Ak,
                                bf16* __restrict__ Av, bf16* __restrict__ Bq,
                                bf16* __restrict__ Bk, bf16* __restrict__ Bv,
                                bf16* __restrict__ Bo)
{
    int which = blockIdx.y;
    int idx   = blockIdx.x * blockDim.x + threadIdx.x;
    if (which < 3) {  // A-pack: [hi | lo | hi]
        const float* src = (which == 0) ? q : (which == 1) ? k : v;
        bf16*        dst = (which == 0) ? Aq : (which == 1) ? Ak : Av;
        if (idx >= NTOK * DD) return;
        int m = idx / DD, c = idx % DD;
        float x = src[idx];
        bf16 hi = __float2bfloat16(x);
        bf16 lo = __float2bfloat16(x - __bfloat162float(hi));
        size_t r = (size_t)m * 3 * DD;
        dst[r + c] = hi; dst[r + DD + c] = lo; dst[r + 2 * DD + c] = hi;
    } else if (which < 6) {  // B-pack: [hi ; hi ; lo]
        const float* src = (which == 3) ? Wq : (which == 4) ? Wk : Wv;
        bf16*        dst = (which == 3) ? Bq : (which == 4) ? Bk : Bv;
        if (idx >= DD * DH) return;
        int kk = idx / DH, n = idx % DH;
        float x = src[idx];
        bf16 hi = __float2bfloat16(x);
        bf16 lo = __float2bfloat16(x - __bfloat162float(hi));
        dst[(size_t)kk * DH + n]            = hi;
        dst[(size_t)(DD + kk) * DH + n]     = hi;
        dst[(size_t)(2 * DD + kk) * DH + n] = lo;
    } else {  // Wo pack: [hi ; hi ; lo]
        if (idx >= DH * DD) return;
        int kk = idx / DD, n = idx % DD;
        float x = Wo[idx];
        bf16 hi = __float2bfloat16(x);
        bf16 lo = __float2bfloat16(x - __bfloat162float(hi));
        Bo[(size_t)kk * DD + n]            = hi;
        Bo[(size_t)(DH + kk) * DD + n]     = hi;
        Bo[(size_t)(2 * DH + kk) * DD + n] = lo;
    }
}

// ---------------------------------------------------------------------------
// bf16 tensor-core GEMM:  C = A2 @ B2 + bias  (fp32 out)
// ---------------------------------------------------------------------------
template<int BM, int BN, int BK, int WM, int WN>
__global__ void __launch_bounds__(256, 2)
gemm_bf16_kernel(const bf16* __restrict__ A, const bf16* __restrict__ B,
                 const float* __restrict__ bias, float* __restrict__ C,
                 int M, int N, int K2)
{
    constexpr int WARPS_M = BM / WM, WARPS_N = BN / WN;
    static_assert(WARPS_M * WARPS_N == 8, "8 warps");
    constexpr int MT = WM / 16, NT = WN / 8;
    constexpr int LDA = BK + 8, LDB = BN + 8;
    constexpr int A_CH = BM * BK / 8 / 256;
    constexpr int B_CH = BK * BN / 8 / 256;

    __shared__ __align__(16) bf16 As[2][BM * LDA];
    __shared__ __align__(16) bf16 Bs[2][BK * LDB];

    const int tid  = threadIdx.x;
    const int lane = tid & 31, wid = tid >> 5;
    const int wm   = wid % WARPS_M, wn = wid / WARPS_M;
    const int bx   = blockIdx.x, by = blockIdx.y;

    const bf16* Ag = A + (size_t)(by * BM) * K2;
    const bf16* Bg = B + bx * BN;

    float acc[MT][NT][4];
    #pragma unroll
    for (int i = 0; i < MT; i++)
        #pragma unroll
        for (int j = 0; j < NT; j++)
            #pragma unroll
            for (int u = 0; u < 4; u++) acc[i][j][u] = 0.f;

    const int ntile = K2 / BK;

    auto load_tile = [&](int t, int buf) {
        int k0 = t * BK;
        #pragma unroll
        for (int r = 0; r < A_CH; r++) {
            int id = r * 256 + tid;
            int row = id / (BK / 8), c8 = (id % (BK / 8)) * 8;
            cp_async16(&As[buf][row * LDA + c8], Ag + (size_t)row * K2 + k0 + c8);
        }
        #pragma unroll
        for (int r = 0; r < B_CH; r++) {
            int id = r * 256 + tid;
            int row = id / (BN / 8), c8 = (id % (BN / 8)) * 8;
            cp_async16(&Bs[buf][row * LDB + c8], Bg + (size_t)(k0 + row) * N + c8);
        }
        cp_commit();
    };

    load_tile(0, 0);

    for (int t = 0; t < ntile; t++) {
        int cur = t & 1;
        if (t + 1 < ntile) { load_tile(t + 1, (t + 1) & 1); cp_wait<1>(); }
        else               { cp_wait<0>(); }
        __syncthreads();

        #pragma unroll
        for (int ks = 0; ks < BK / 16; ks++) {
            uint32_t af[MT][4];
            #pragma unroll
            for (int mt = 0; mt < MT; mt++) {
                uint32_t addr = smem_u32(&As[cur][(wm * WM + mt * 16 + (lane & 15)) * LDA
                                                  + ks * 16 + (lane >> 4) * 8]);
                ldm_x4(af[mt][0], af[mt][1], af[mt][2], af[mt][3], addr);
            }
            uint32_t bfr[NT][2];
            #pragma unroll
            for (int nt = 0; nt < NT; nt++) {
                uint32_t addr = smem_u32(&Bs[cur][(ks * 16 + (lane & 15)) * LDB
                                                  + wn * WN + nt * 8]);
                ldm_x2_t(bfr[nt][0], bfr[nt][1], addr);
            }
            #pragma unroll
            for (int mt = 0; mt < MT; mt++)
                #pragma unroll
                for (int nt = 0; nt < NT; nt++)
                    mma_bf16(acc[mt][nt], af[mt], bfr[nt][0], bfr[nt][1]);
        }
        __syncthreads();
    }

    const int row0 = by * BM + wm * WM + lane / 4;
    const int col0 = bx * BN + wn * WN + (lane & 3) * 2;
    #pragma unroll
    for (int mt = 0; mt < MT; mt++) {
        #pragma unroll
        for (int nt = 0; nt < NT; nt++) {
            int r = row0 + mt * 16, c = col0 + nt * 8;
            float2 bv = *(const float2*)(bias + c);
            float2 v0 = make_float2(acc[mt][nt][0] + bv.x, acc[mt][nt][1] + bv.y);
            float2 v1 = make_float2(acc[mt][nt][2] + bv.x, acc[mt][nt][3] + bv.y);
            *(float2*)(C + (size_t)r * N + c)       = v0;
            *(float2*)(C + (size_t)(r + 8) * N + c) = v1;
        }
    }
}

// ---------------------------------------------------------------------------
// Tensor-core per-token attention.  One block per token, 256 threads (8 warps).
//
//   S = (Q3/sqrt(128)) @ K3^T  via bf16-split mma  (m128 n128 k48)
//   P = softmax over i (columns), fp32, no max-subtract (|S| <~ 0.3)
//   O = P @ V3                 via bf16-split mma  (m128 n16  k384)
//
// Split complementarity (the R3 bug): A-side packed [hi|lo|hi] along K,
// B-side packed [hi|hi|lo].  A.B = Ahi.Bhi + Alo.Bhi + Ahi.Blo.
//   sQ (A of S):  [hi|lo|hi]     sK (B of S):  [hi|hi|lo]
//   sP (A of AV): [hi|lo|hi]     sVt (B of AV):[hi|hi|lo]
// ---------------------------------------------------------------------------
#define LQK 56    // sQ/sK row stride (48 data + 8 pad)
#define LPV 392   // sVt/sP row stride (384 data + 8 pad)
#define LSS 132   // sS row stride (fp32)

__global__ void __launch_bounds__(256, 1)
attention_tc_kernel(const float* __restrict__ Qp,
                    const float* __restrict__ Kp,
                    const float* __restrict__ Vp,
                    bf16* __restrict__ Obf)
{
    extern __shared__ char smem_raw[];
    bf16* sQ   = (bf16*)smem_raw;            // [128][56]
    bf16* sK   = sQ  + 128 * LQK;            // [128][56]
    bf16* sVt  = sK  + 128 * LQK;            // [16][392]
    bf16* sP   = sVt + 16 * LPV;             // [128][392]
    float* sS  = (float*)(sP + 128 * LPV);   // [128][132]
    float* sRed = sS + 128 * LSS;            // [2][128]

    const int n    = blockIdx.x;
    const int tid  = threadIdx.x;
    const int lane = tid & 31;
    const int warp = tid >> 5;

    const float* qrow = Qp + (size_t)n * DH;
    const float* krow = Kp + (size_t)n * DH;
    const float* vrow = Vp + (size_t)n * DH;
    const float scale = 0.08838834764831845f;  // 1/sqrt(128), folded into Q

    // ---- convert fp32 rows -> split bf16 operand layouts ----
    #pragma unroll
    for (int r = 0; r < 2; r++) {
        int f4 = r * 256 + tid;
        int f  = f4 * 4;
        int i  = f >> 4;          // token-feature row (0..127)
        int h  = f & 15;          // 0,4,8,12
        float4 q4 = *(const float4*)(qrow + f);
        float4 k4 = *(const float4*)(krow + f);
        float4 v4 = *(const float4*)(vrow + f);

        __nv_bfloat162 hv, lv;
        // Q (scaled), A-side: [hi(0..15) | lo(16..31) | hi(32..47)]
        split2(q4.x * scale, q4.y * scale, hv, lv);
        *(__nv_bfloat162*)(sQ + i * LQK + h)      = hv;
        *(__nv_bfloat162*)(sQ + i * LQK + 16 + h) = lv;
        *(__nv_bfloat162*)(sQ + i * LQK + 32 + h) = hv;
        split2(q4.z * scale, q4.w * scale, hv, lv);
        *(__nv_bfloat162*)(sQ + i * LQK + h + 2)      = hv;
        *(__nv_bfloat162*)(sQ + i * LQK + 16 + h + 2) = lv;
        *(__nv_bfloat162*)(sQ + i * LQK + 32 + h + 2) = hv;
        // K, B-side: [hi(0..15) | hi(16..31) | lo(32..47)]   (FIXED)
        split2(k4.x, k4.y, hv, lv);
        *(__nv_bfloat162*)(sK + i * LQK + h)      = hv;
        *(__nv_bfloat162*)(sK + i * LQK + 16 + h) = hv;
        *(__nv_bfloat162*)(sK + i * LQK + 32 + h) = lv;
        split2(k4.z, k4.w, hv, lv);
        *(__nv_bfloat162*)(sK + i * LQK + h + 2)      = hv;
        *(__nv_bfloat162*)(sK + i * LQK + 16 + h + 2) = hv;
        *(__nv_bfloat162*)(sK + i * LQK + 32 + h + 2) = lv;
        // V transposed, B-side: [hi(0..127) | hi(128..255) | lo(256..383)]  (FIXED)
        float vv[4] = {v4.x, v4.y, v4.z, v4.w};
        #pragma unroll
        for (int u = 0; u < 4; u++) {
            bf16 hi = __float2bfloat16(vv[u]);
            bf16 lo = __float2bfloat16(vv[u] - __bfloat162float(hi));
            sVt[(h + u) * LPV + i]       = hi;
            sVt[(h + u) * LPV + 128 + i] = hi;
            sVt[(h + u) * LPV + 256 + i] = lo;
        }
    }
    __syncthreads();

    // ---- scores: m128 n128 k48; warp owns m-tile [16*warp, 16*warp+16) ----
    {
        uint32_t af[3][4];
        #pragma unroll
        for (int ks = 0; ks < 3; ks++) {
            uint32_t addr = smem_u32(&sQ[(warp * 16 + (lane & 15)) * LQK
                                         + ks * 16 + (lane >> 4) * 8]);
            ldm_x4(af[ks][0], af[ks][1], af[ks][2], af[ks][3], addr);
        }
        float accS[16][4];
        #pragma unroll
        for (int t = 0; t < 16; t++)
            #pragma unroll
            for (int u = 0; u < 4; u++) accS[t][u] = 0.f;

        const int brow = (lane & 7) + ((lane >> 4) << 3);
        const int bcol = ((lane >> 3) & 1) << 3;
        #pragma unroll
        for (int jt = 0; jt < 8; jt++) {
            #pragma unroll
            for (int ks = 0; ks < 3; ks++) {
                uint32_t b0, b1, b2, b3;
                uint32_t addr = smem_u32(&sK[(jt * 16 + brow) * LQK + ks * 16 + bcol]);
                ldm_x4(b0, b1, b2, b3, addr);
                mma_bf16(accS[2 * jt],     af[ks], b0, b1);
                mma_bf16(accS[2 * jt + 1], af[ks], b2, b3);
            }
        }
        const int r0 = warp * 16 + lane / 4;
        const int c0 = (lane & 3) * 2;
        #pragma unroll
        for (int t = 0; t < 16; t++) {
            *(float2*)&sS[r0 * LSS + t * 8 + c0]       = make_float2(accS[t][0], accS[t][1]);
            *(float2*)&sS[(r0 + 8) * LSS + t * 8 + c0] = make_float2(accS[t][2], accS[t][3]);
        }
    }
    __syncthreads();

    // ---- softmax over i per column j; no max-subtract (|S| tiny) ----
    {
        const int j    = tid & 127;
        const int half = tid >> 7;
        const int ib   = half * 64;
        float s = 0.f;
        #pragma unroll 4
        for (int ii = 0; ii < 64; ii++) {
            float e = __expf(sS[(ib + ii) * LSS + j]);
            sS[(ib + ii) * LSS + j] = e;
            s += e;
        }
        sRed[half * 128 + j] = s;
        __syncthreads();
        const float inv = 1.f / (sRed[j] + sRed[128 + j]);
        #pragma unroll 4
        for (int ii = 0; ii < 64; ii++) {
            float p = sS[(ib + ii) * LSS + j] * inv;
            bf16 hi = __float2bfloat16(p);
            bf16 lo = __float2bfloat16(p - __bfloat162float(hi));
            sP[(ib + ii) * LPV + j]       = hi;
            sP[(ib + ii) * LPV + 128 + j] = lo;
            sP[(ib + ii) * LPV + 256 + j] = hi;
        }
    }
    __syncthreads();

    // ---- AV: m128 n16 k384; A = sP[i][k], B = sVt[h][k] ----
    {
        float accO[2][4];
        #pragma unroll
        for (int t = 0; t < 2; t++)
            #pragma unroll
            for (int u = 0; u < 4; u++) accO[t][u] = 0.f;

        const int arow = (lane & 15);
        const int acol = (lane >> 4) * 8;
        const int brow = (lane & 7) + ((lane >> 4) << 3);
        const int bcol = ((lane >> 3) & 1) << 3;
        #pragma unroll
        for (int ks = 0; ks < 24; ks++) {
            uint32_t a[4];
            uint32_t addr = smem_u32(&sP[(warp * 16 + arow) * LPV + ks * 16 + acol]);
            ldm_x4(a[0], a[1], a[2], a[3], addr);
            uint32_t b0, b1, b2, b3;
            addr = smem_u32(&sVt[brow * LPV + ks * 16 + bcol]);
            ldm_x4(b0, b1, b2, b3, addr);
            mma_bf16(accO[0], a, b0, b1);
            mma_bf16(accO[1], a, b2, b3);
        }

        // epilogue: write packed [hi|lo|hi] rows of length 3*DH to global
        bf16* obase = Obf + (size_t)n * (3 * DH);
        const int r0 = warp * 16 + lane / 4;
        const int c0 = (lane & 3) * 2;
        #pragma unroll
        for (int nt = 0; nt < 2; nt++) {
            #pragma unroll
            for (int rr = 0; rr < 2; rr++) {
                int i = r0 + rr * 8;
                int h = nt * 8 + c0;
                int f = i * HH + h;
                __nv_bfloat162 hv, lv;
                split2(accO[nt][2 * rr], accO[nt][2 * rr + 1], hv, lv);
                *(__nv_bfloat162*)(obase + f)            = hv;
                *(__nv_bfloat162*)(obase + DH + f)       = lv;
                *(__nv_bfloat162*)(obase + 2 * DH + f)   = hv;
            }
        }
    }
}

// ---------------------------------------------------------------------------
// Launcher
// ---------------------------------------------------------------------------
#define ATT2_SMEM_BYTES ((128*LQK + 128*LQK + 16*LPV + 128*LPV) * 2 + (128*LSS + 256) * 4)

extern "C" void kernel_launch(void* const* d_in, const int* in_sizes, int n_in,
                              void* d_out, int out_size)
{
    const float* q  = (const float*)d_in[0];
    const float* k  = (const float*)d_in[1];
    const float* v  = (const float*)d_in[2];
    const float* Wq = (const float*)d_in[3];
    const float* bq = (const float*)d_in[4];
    const float* Wk = (const float*)d_in[5];
    const float* bk = (const float*)d_in[6];
    const float* Wv = (const float*)d_in[7];
    const float* bv = (const float*)d_in[8];
    const float* Wo = (const float*)d_in[9];
    const float* bo = (const float*)d_in[10];
    float* out = (float*)d_out;
    (void)in_sizes; (void)n_in; (void)out_size;

    float *Qp, *Kp, *Vp;
    bf16 *Aq, *Ak, *Av, *Bq, *Bk, *Bv, *Bo, *Obf;
    cudaGetSymbolAddress((void**)&Qp,  g_Qp);
    cudaGetSymbolAddress((void**)&Kp,  g_Kp);
    cudaGetSymbolAddress((void**)&Vp,  g_Vp);
    cudaGetSymbolAddress((void**)&Aq,  g_Aq);
    cudaGetSymbolAddress((void**)&Ak,  g_Ak);
    cudaGetSymbolAddress((void**)&Av,  g_Av);
    cudaGetSymbolAddress((void**)&Bq,  g_Bq);
    cudaGetSymbolAddress((void**)&Bk,  g_Bk);
    cudaGetSymbolAddress((void**)&Bv,  g_Bv);
    cudaGetSymbolAddress((void**)&Bo,  g_Bo);
    cudaGetSymbolAddress((void**)&Obf, g_Obf);

    cudaFuncSetAttribute(attention_tc_kernel,
                         cudaFuncAttributeMaxDynamicSharedMemorySize,
                         ATT2_SMEM_BYTES);

    // 0) pack inputs/weights (one launch; y selects tensor)
    dim3 gpack((NTOK * DD + 255) / 256, 7);
    pack_all_kernel<<<gpack, 256>>>(q, k, v, Wq, Wk, Wv, Wo,
                                    Aq, Ak, Av, Bq, Bk, Bv, Bo);

    // 1) projections: [8192,384]bf16 @ [384,2048]bf16 -> fp32
    dim3 gproj(DH / 128, NTOK / 128);
    gemm_bf16_kernel<128,128,32,64,32><<<gproj, 256>>>(Aq, Bq, bq, Qp, NTOK, DH, 3 * DD);
    gemm_bf16_kernel<128,128,32,64,32><<<gproj, 256>>>(Ak, Bk, bk, Kp, NTOK, DH, 3 * DD);
    gemm_bf16_kernel<128,128,32,64,32><<<gproj, 256>>>(Av, Bv, bv, Vp, NTOK, DH, 3 * DD);

    // 2) per-token attention on tensor cores (emits packed bf16 output)
    attention_tc_kernel<<<NTOK, 256, ATT2_SMEM_BYTES>>>(Qp, Kp, Vp, Obf);

    // 3) output projection: [8192,6144]bf16 @ [6144,128]bf16 -> fp32
    dim3 gout(DD / 64, NTOK / 64);
    gemm_bf16_kernel<64,64,64,32,16><<<gout, 256>>>(Obf, Bo, bo, out, NTOK, DD, 3 * DH);
}

// round 5
// speedup vs baseline: 1.5311x; 1.5311x over previous
#include <cuda_runtime.h>
#include <cuda_bf16.h>
#include <cstdint>

// Problem constants
#define NTOK 8192
#define DD   128
#define HH   16
#define DH   2048   // DD*HH

typedef __nv_bfloat16 bf16;

// ---------------------------------------------------------------------------
// Device scratch (no cudaMalloc allowed).
// ---------------------------------------------------------------------------
__device__ float g_Qp[(size_t)NTOK * DH];      // fp32 projections (attention input)
__device__ float g_Kp[(size_t)NTOK * DH];
__device__ float g_Vp[(size_t)NTOK * DH];

__device__ bf16  g_Aq[(size_t)NTOK * 3 * DD];  // packed [hi|lo|hi] inputs, K=384
__device__ bf16  g_Ak[(size_t)NTOK * 3 * DD];
__device__ bf16  g_Av[(size_t)NTOK * 3 * DD];
__device__ bf16  g_Bq[(size_t)3 * DD * DH];    // packed [hi;hi;lo] weights
__device__ bf16  g_Bk[(size_t)3 * DD * DH];
__device__ bf16  g_Bv[(size_t)3 * DD * DH];
__device__ bf16  g_Bo[(size_t)3 * DH * DD];    // Wo packed, K2=6144, N=128
__device__ bf16  g_Obf[(size_t)NTOK * 3 * DH]; // attention out, packed hi|lo|hi

// ---------------------------------------------------------------------------
// PTX helpers
// ---------------------------------------------------------------------------
__device__ __forceinline__ uint32_t smem_u32(const void* p) {
    return (uint32_t)__cvta_generic_to_shared(p);
}
__device__ __forceinline__ void ldm_x4(uint32_t& r0, uint32_t& r1, uint32_t& r2,
                                       uint32_t& r3, uint32_t addr) {
    asm volatile("ldmatrix.sync.aligned.m8n8.x4.shared.b16 {%0,%1,%2,%3}, [%4];\n"
                 : "=r"(r0), "=r"(r1), "=r"(r2), "=r"(r3) : "r"(addr));
}
__device__ __forceinline__ void ldm_x2_t(uint32_t& r0, uint32_t& r1, uint32_t addr) {
    asm volatile("ldmatrix.sync.aligned.m8n8.x2.trans.shared.b16 {%0,%1}, [%2];\n"
                 : "=r"(r0), "=r"(r1) : "r"(addr));
}
__device__ __forceinline__ void mma_bf16(float c[4], const uint32_t a[4],
                                         uint32_t b0, uint32_t b1) {
    asm volatile(
        "mma.sync.aligned.m16n8k16.row.col.f32.bf16.bf16.f32 "
        "{%0,%1,%2,%3}, {%4,%5,%6,%7}, {%8,%9}, {%0,%1,%2,%3};\n"
        : "+f"(c[0]), "+f"(c[1]), "+f"(c[2]), "+f"(c[3])
        : "r"(a[0]), "r"(a[1]), "r"(a[2]), "r"(a[3]), "r"(b0), "r"(b1));
}
__device__ __forceinline__ void cp_async16(void* dst, const void* src) {
    asm volatile("cp.async.cg.shared.global [%0], [%1], 16;\n"
                 :: "r"(smem_u32(dst)), "l"(src));
}
__device__ __forceinline__ void cp_commit() {
    asm volatile("cp.async.commit_group;\n");
}
template<int N>
__device__ __forceinline__ void cp_wait() {
    asm volatile("cp.async.wait_group %0;\n" :: "n"(N));
}

// split a float pair into bf16 (hi, lo) pairs
__device__ __forceinline__ void split2(float a, float b,
                                       __nv_bfloat162& hv, __nv_bfloat162& lv) {
    bf16 h0 = __float2bfloat16(a), h1 = __float2bfloat16(b);
    hv = __halves2bfloat162(h0, h1);
    lv = __halves2bfloat162(__float2bfloat16(a - __bfloat162float(h0)),
                            __float2bfloat16(b - __bfloat162float(h1)));
}

// ---------------------------------------------------------------------------
// Unified pack kernel.  blockIdx.y selects tensor:
//   0..2 : A-pack (q,k,v)   M=NTOK, K=DD      -> [hi | lo | hi] along K
//   3..5 : B-pack (Wq,Wk,Wv) K=DD,  N=DH      -> [hi ; hi ; lo] along K
//   6    : B-pack (Wo)       K=DH,  N=DD
// ---------------------------------------------------------------------------
__global__ void pack_all_kernel(const float* __restrict__ q, const float* __restrict__ k,
                                const float* __restrict__ v, const float* __restrict__ Wq,
                                const float* __restrict__ Wk, const float* __restrict__ Wv,
                                const float* __restrict__ Wo,
                                bf16* __restrict__ Aq, bf16* __restrict__ Ak,
                                bf16* __restrict__ Av, bf16* __restrict__ Bq,
                                bf16* __restrict__ Bk, bf16* __restrict__ Bv,
                                bf16* __restrict__ Bo)
{
    int which = blockIdx.y;
    int idx   = blockIdx.x * blockDim.x + threadIdx.x;
    if (which < 3) {  // A-pack: [hi | lo | hi]
        const float* src = (which == 0) ? q : (which == 1) ? k : v;
        bf16*        dst = (which == 0) ? Aq : (which == 1) ? Ak : Av;
        if (idx >= NTOK * DD) return;
        int m = idx / DD, c = idx % DD;
        float x = src[idx];
        bf16 hi = __float2bfloat16(x);
        bf16 lo = __float2bfloat16(x - __bfloat162float(hi));
        size_t r = (size_t)m * 3 * DD;
        dst[r + c] = hi; dst[r + DD + c] = lo; dst[r + 2 * DD + c] = hi;
    } else if (which < 6) {  // B-pack: [hi ; hi ; lo]
        const float* src = (which == 3) ? Wq : (which == 4) ? Wk : Wv;
        bf16*        dst = (which == 3) ? Bq : (which == 4) ? Bk : Bv;
        if (idx >= DD * DH) return;
        int kk = idx / DH, n = idx % DH;
        float x = src[idx];
        bf16 hi = __float2bfloat16(x);
        bf16 lo = __float2bfloat16(x - __bfloat162float(hi));
        dst[(size_t)kk * DH + n]            = hi;
        dst[(size_t)(DD + kk) * DH + n]     = hi;
        dst[(size_t)(2 * DD + kk) * DH + n] = lo;
    } else {  // Wo pack: [hi ; hi ; lo]
        if (idx >= DH * DD) return;
        int kk = idx / DD, n = idx % DD;
        float x = Wo[idx];
        bf16 hi = __float2bfloat16(x);
        bf16 lo = __float2bfloat16(x - __bfloat162float(hi));
        Bo[(size_t)kk * DD + n]            = hi;
        Bo[(size_t)(DH + kk) * DD + n]     = hi;
        Bo[(size_t)(2 * DH + kk) * DD + n] = lo;
    }
}

// ---------------------------------------------------------------------------
// bf16 tensor-core GEMM:  C = A2 @ B2 + bias  (fp32 out)
// ---------------------------------------------------------------------------
template<int BM, int BN, int BK, int WM, int WN>
__global__ void __launch_bounds__(256, 2)
gemm_bf16_kernel(const bf16* __restrict__ A, const bf16* __restrict__ B,
                 const float* __restrict__ bias, float* __restrict__ C,
                 int M, int N, int K2)
{
    constexpr int WARPS_M = BM / WM, WARPS_N = BN / WN;
    static_assert(WARPS_M * WARPS_N == 8, "8 warps");
    constexpr int MT = WM / 16, NT = WN / 8;
    constexpr int LDA = BK + 8, LDB = BN + 8;
    constexpr int A_CH = BM * BK / 8 / 256;
    constexpr int B_CH = BK * BN / 8 / 256;

    __shared__ __align__(16) bf16 As[2][BM * LDA];
    __shared__ __align__(16) bf16 Bs[2][BK * LDB];

    const int tid  = threadIdx.x;
    const int lane = tid & 31, wid = tid >> 5;
    const int wm   = wid % WARPS_M, wn = wid / WARPS_M;
    const int bx   = blockIdx.x, by = blockIdx.y;

    const bf16* Ag = A + (size_t)(by * BM) * K2;
    const bf16* Bg = B + bx * BN;

    float acc[MT][NT][4];
    #pragma unroll
    for (int i = 0; i < MT; i++)
        #pragma unroll
        for (int j = 0; j < NT; j++)
            #pragma unroll
            for (int u = 0; u < 4; u++) acc[i][j][u] = 0.f;

    const int ntile = K2 / BK;

    auto load_tile = [&](int t, int buf) {
        int k0 = t * BK;
        #pragma unroll
        for (int r = 0; r < A_CH; r++) {
            int id = r * 256 + tid;
            int row = id / (BK / 8), c8 = (id % (BK / 8)) * 8;
            cp_async16(&As[buf][row * LDA + c8], Ag + (size_t)row * K2 + k0 + c8);
        }
        #pragma unroll
        for (int r = 0; r < B_CH; r++) {
            int id = r * 256 + tid;
            int row = id / (BN / 8), c8 = (id % (BN / 8)) * 8;
            cp_async16(&Bs[buf][row * LDB + c8], Bg + (size_t)(k0 + row) * N + c8);
        }
        cp_commit();
    };

    load_tile(0, 0);

    for (int t = 0; t < ntile; t++) {
        int cur = t & 1;
        if (t + 1 < ntile) { load_tile(t + 1, (t + 1) & 1); cp_wait<1>(); }
        else               { cp_wait<0>(); }
        __syncthreads();

        #pragma unroll
        for (int ks = 0; ks < BK / 16; ks++) {
            uint32_t af[MT][4];
            #pragma unroll
            for (int mt = 0; mt < MT; mt++) {
                uint32_t addr = smem_u32(&As[cur][(wm * WM + mt * 16 + (lane & 15)) * LDA
                                                  + ks * 16 + (lane >> 4) * 8]);
                ldm_x4(af[mt][0], af[mt][1], af[mt][2], af[mt][3], addr);
            }
            uint32_t bfr[NT][2];
            #pragma unroll
            for (int nt = 0; nt < NT; nt++) {
                uint32_t addr = smem_u32(&Bs[cur][(ks * 16 + (lane & 15)) * LDB
                                                  + wn * WN + nt * 8]);
                ldm_x2_t(bfr[nt][0], bfr[nt][1], addr);
            }
            #pragma unroll
            for (int mt = 0; mt < MT; mt++)
                #pragma unroll
                for (int nt = 0; nt < NT; nt++)
                    mma_bf16(acc[mt][nt], af[mt], bfr[nt][0], bfr[nt][1]);
        }
        __syncthreads();
    }

    const int row0 = by * BM + wm * WM + lane / 4;
    const int col0 = bx * BN + wn * WN + (lane & 3) * 2;
    #pragma unroll
    for (int mt = 0; mt < MT; mt++) {
        #pragma unroll
        for (int nt = 0; nt < NT; nt++) {
            int r = row0 + mt * 16, c = col0 + nt * 8;
            float2 bv = *(const float2*)(bias + c);
            float2 v0 = make_float2(acc[mt][nt][0] + bv.x, acc[mt][nt][1] + bv.y);
            float2 v1 = make_float2(acc[mt][nt][2] + bv.x, acc[mt][nt][3] + bv.y);
            *(float2*)(C + (size_t)r * N + c)       = v0;
            *(float2*)(C + (size_t)(r + 8) * N + c) = v1;
        }
    }
}

// ---------------------------------------------------------------------------
// Tensor-core per-token attention, v2 (occupancy 2).
//
//   S = (Q3/sqrt(128)) @ K3^T       bf16-split mma, m128 n128 k48
//   E = exp(S)                      computed in S-mma epilogue registers
//   c[j] = sum_i E[i][j]            shfl + smem reduce
//   V'[j][h] = V[j][h] / c[j]       normalize V instead of P (axis-1 softmax!)
//   O = E @ V'                      2-pass bf16-split mma, m128 n16
//
// Split complementarity: A-side [hi|lo], B-side [hi|hi] (+ 3rd term hi x lo).
// smem: sQ[128][56] sK[128][56] sP[128][264]=[E_hi|E_lo] sVt[16][392]=[Vhi|Vhi|Vlo]
//       sPart[8][128] sInv[128]   total 113408 B -> 2 CTAs/SM
// ---------------------------------------------------------------------------
#define LQK 56    // sQ/sK row stride (48 data + 8 pad)
#define LP  264   // sP row stride (256 data + 8 pad)
#define LVT 392   // sVt row stride (384 data + 8 pad)

__global__ void __launch_bounds__(256, 2)
attention_tc_kernel(const float* __restrict__ Qp,
                    const float* __restrict__ Kp,
                    const float* __restrict__ Vp,
                    bf16* __restrict__ Obf)
{
    extern __shared__ char smem_raw[];
    bf16* sQ    = (bf16*)smem_raw;            // [128][56]
    bf16* sK    = sQ + 128 * LQK;             // [128][56]
    bf16* sP    = sK + 128 * LQK;             // [128][264]
    bf16* sVt   = sP + 128 * LP;              // [16][392]
    float* sPart = (float*)(sVt + 16 * LVT);  // [8][128]
    float* sInv  = sPart + 8 * 128;           // [128]

    const int n    = blockIdx.x;
    const int tid  = threadIdx.x;
    const int lane = tid & 31;
    const int warp = tid >> 5;

    const float* qrow = Qp + (size_t)n * DH;
    const float* krow = Kp + (size_t)n * DH;
    const float* vrow = Vp + (size_t)n * DH;
    const float scale = 0.08838834764831845f;  // 1/sqrt(128), folded into Q

    // ---- phase 1: convert Q, K -> split bf16 smem operands ----
    #pragma unroll
    for (int r = 0; r < 2; r++) {
        int f4 = r * 256 + tid;
        int f  = f4 * 4;
        int i  = f >> 4;          // token-feature row (0..127)
        int h  = f & 15;          // 0,4,8,12
        float4 q4 = *(const float4*)(qrow + f);
        float4 k4 = *(const float4*)(krow + f);

        __nv_bfloat162 hv, lv;
        // Q (scaled), A-side: [hi(0..15) | lo(16..31) | hi(32..47)]
        split2(q4.x * scale, q4.y * scale, hv, lv);
        *(__nv_bfloat162*)(sQ + i * LQK + h)      = hv;
        *(__nv_bfloat162*)(sQ + i * LQK + 16 + h) = lv;
        *(__nv_bfloat162*)(sQ + i * LQK + 32 + h) = hv;
        split2(q4.z * scale, q4.w * scale, hv, lv);
        *(__nv_bfloat162*)(sQ + i * LQK + h + 2)      = hv;
        *(__nv_bfloat162*)(sQ + i * LQK + 16 + h + 2) = lv;
        *(__nv_bfloat162*)(sQ + i * LQK + 32 + h + 2) = hv;
        // K, B-side: [hi | hi | lo]
        split2(k4.x, k4.y, hv, lv);
        *(__nv_bfloat162*)(sK + i * LQK + h)      = hv;
        *(__nv_bfloat162*)(sK + i * LQK + 16 + h) = hv;
        *(__nv_bfloat162*)(sK + i * LQK + 32 + h) = lv;
        split2(k4.z, k4.w, hv, lv);
        *(__nv_bfloat162*)(sK + i * LQK + h + 2)      = hv;
        *(__nv_bfloat162*)(sK + i * LQK + 16 + h + 2) = hv;
        *(__nv_bfloat162*)(sK + i * LQK + 32 + h + 2) = lv;
    }
    __syncthreads();

    const int r0 = warp * 16 + lane / 4;   // fragment row
    const int c0 = (lane & 3) * 2;         // fragment col pair base

    // ---- phase 2: S-mma + exp + E->sP + column-sum partials ----
    {
        uint32_t af[3][4];
        #pragma unroll
        for (int ks = 0; ks < 3; ks++) {
            uint32_t addr = smem_u32(&sQ[(warp * 16 + (lane & 15)) * LQK
                                         + ks * 16 + (lane >> 4) * 8]);
            ldm_x4(af[ks][0], af[ks][1], af[ks][2], af[ks][3], addr);
        }
        float accS[16][4];
        #pragma unroll
        for (int t = 0; t < 16; t++)
            #pragma unroll
            for (int u = 0; u < 4; u++) accS[t][u] = 0.f;

        const int brow = (lane & 7) + ((lane >> 4) << 3);
        const int bcol = ((lane >> 3) & 1) << 3;
        #pragma unroll
        for (int jt = 0; jt < 8; jt++) {
            #pragma unroll
            for (int ks = 0; ks < 3; ks++) {
                uint32_t b0, b1, b2, b3;
                uint32_t addr = smem_u32(&sK[(jt * 16 + brow) * LQK + ks * 16 + bcol]);
                ldm_x4(b0, b1, b2, b3, addr);
                mma_bf16(accS[2 * jt],     af[ks], b0, b1);
                mma_bf16(accS[2 * jt + 1], af[ks], b2, b3);
            }
        }

        // epilogue: E = exp(S); write [E_hi|E_lo] to sP; partial column sums
        float cs0[16], cs1[16];
        #pragma unroll
        for (int t = 0; t < 16; t++) {
            float e0 = __expf(accS[t][0]);
            float e1 = __expf(accS[t][1]);
            float e2 = __expf(accS[t][2]);
            float e3 = __expf(accS[t][3]);
            __nv_bfloat162 hv, lv;
            split2(e0, e1, hv, lv);
            *(__nv_bfloat162*)(sP + r0 * LP + t * 8 + c0)       = hv;
            *(__nv_bfloat162*)(sP + r0 * LP + 128 + t * 8 + c0) = lv;
            split2(e2, e3, hv, lv);
            *(__nv_bfloat162*)(sP + (r0 + 8) * LP + t * 8 + c0)       = hv;
            *(__nv_bfloat162*)(sP + (r0 + 8) * LP + 128 + t * 8 + c0) = lv;
            cs0[t] = e0 + e2;   // rows r0, r0+8 contribution to col t*8+c0
            cs1[t] = e1 + e3;   // ... to col t*8+c0+1
        }
        // reduce over the 8 row-groups within warp (lane bits 2..4)
        #pragma unroll
        for (int t = 0; t < 16; t++) {
            cs0[t] += __shfl_xor_sync(0xffffffff, cs0[t], 4);
            cs0[t] += __shfl_xor_sync(0xffffffff, cs0[t], 8);
            cs0[t] += __shfl_xor_sync(0xffffffff, cs0[t], 16);
            cs1[t] += __shfl_xor_sync(0xffffffff, cs1[t], 4);
            cs1[t] += __shfl_xor_sync(0xffffffff, cs1[t], 8);
            cs1[t] += __shfl_xor_sync(0xffffffff, cs1[t], 16);
        }
        if (lane < 4) {
            #pragma unroll
            for (int t = 0; t < 16; t++) {
                sPart[warp * 128 + t * 8 + c0]     = cs0[t];
                sPart[warp * 128 + t * 8 + c0 + 1] = cs1[t];
            }
        }
    }
    __syncthreads();

    // ---- phase 3: finish column sums -> sInv ----
    if (tid < 128) {
        float c = 0.f;
        #pragma unroll
        for (int w = 0; w < 8; w++) c += sPart[w * 128 + tid];
        sInv[tid] = 1.f / c;
    }
    __syncthreads();

    // ---- phase 4: V' = V / c, split to sVt = [V'hi | V'hi | V'lo] ----
    #pragma unroll
    for (int r = 0; r < 2; r++) {
        int f4 = r * 256 + tid;
        int f  = f4 * 4;
        int i  = f >> 4;          // V row j
        int h  = f & 15;
        float4 v4 = *(const float4*)(vrow + f);
        float inv = sInv[i];
        float vv[4] = {v4.x * inv, v4.y * inv, v4.z * inv, v4.w * inv};
        #pragma unroll
        for (int u = 0; u < 4; u++) {
            bf16 hi = __float2bfloat16(vv[u]);
            bf16 lo = __float2bfloat16(vv[u] - __bfloat162float(hi));
            sVt[(h + u) * LVT + i]       = hi;
            sVt[(h + u) * LVT + 128 + i] = hi;
            sVt[(h + u) * LVT + 256 + i] = lo;
        }
    }
    __syncthreads();

    // ---- phase 5: AV, 2-pass: k=256 (Ehi.Vhi + Elo.Vhi) + k=128 (Ehi.Vlo) ----
    {
        float accO[2][4];
        #pragma unroll
        for (int t = 0; t < 2; t++)
            #pragma unroll
            for (int u = 0; u < 4; u++) accO[t][u] = 0.f;

        const int arow = (lane & 15);
        const int acol = (lane >> 4) * 8;
        const int brow = (lane & 7) + ((lane >> 4) << 3);
        const int bcol = ((lane >> 3) & 1) << 3;
        #pragma unroll
        for (int ks = 0; ks < 24; ks++) {
            const int aks = ks & 15;   // 0..15 then 0..7 (reuse E_hi for V_lo pass)
            uint32_t a[4];
            uint32_t addr = smem_u32(&sP[(warp * 16 + arow) * LP + aks * 16 + acol]);
            ldm_x4(a[0], a[1], a[2], a[3], addr);
            uint32_t b0, b1, b2, b3;
            addr = smem_u32(&sVt[brow * LVT + ks * 16 + bcol]);
            ldm_x4(b0, b1, b2, b3, addr);
            mma_bf16(accO[0], a, b0, b1);
            mma_bf16(accO[1], a, b2, b3);
        }

        // epilogue: write packed [hi|lo|hi] rows of length 3*DH to global
        bf16* obase = Obf + (size_t)n * (3 * DH);
        #pragma unroll
        for (int nt = 0; nt < 2; nt++) {
            #pragma unroll
            for (int rr = 0; rr < 2; rr++) {
                int i = r0 + rr * 8;
                int h = nt * 8 + c0;
                int f = i * HH + h;
                __nv_bfloat162 hv, lv;
                split2(accO[nt][2 * rr], accO[nt][2 * rr + 1], hv, lv);
                *(__nv_bfloat162*)(obase + f)            = hv;
                *(__nv_bfloat162*)(obase + DH + f)       = lv;
                *(__nv_bfloat162*)(obase + 2 * DH + f)   = hv;
            }
        }
    }
}

// ---------------------------------------------------------------------------
// Launcher
// ---------------------------------------------------------------------------
#define ATT_SMEM_BYTES ((128*LQK + 128*LQK + 128*LP + 16*LVT) * 2 + (8*128 + 128) * 4)

extern "C" void kernel_launch(void* const* d_in, const int* in_sizes, int n_in,
                              void* d_out, int out_size)
{
    const float* q  = (const float*)d_in[0];
    const float* k  = (const float*)d_in[1];
    const float* v  = (const float*)d_in[2];
    const float* Wq = (const float*)d_in[3];
    const float* bq = (const float*)d_in[4];
    const float* Wk = (const float*)d_in[5];
    const float* bk = (const float*)d_in[6];
    const float* Wv = (const float*)d_in[7];
    const float* bv = (const float*)d_in[8];
    const float* Wo = (const float*)d_in[9];
    const float* bo = (const float*)d_in[10];
    float* out = (float*)d_out;
    (void)in_sizes; (void)n_in; (void)out_size;

    float *Qp, *Kp, *Vp;
    bf16 *Aq, *Ak, *Av, *Bq, *Bk, *Bv, *Bo, *Obf;
    cudaGetSymbolAddress((void**)&Qp,  g_Qp);
    cudaGetSymbolAddress((void**)&Kp,  g_Kp);
    cudaGetSymbolAddress((void**)&Vp,  g_Vp);
    cudaGetSymbolAddress((void**)&Aq,  g_Aq);
    cudaGetSymbolAddress((void**)&Ak,  g_Ak);
    cudaGetSymbolAddress((void**)&Av,  g_Av);
    cudaGetSymbolAddress((void**)&Bq,  g_Bq);
    cudaGetSymbolAddress((void**)&Bk,  g_Bk);
    cudaGetSymbolAddress((void**)&Bv,  g_Bv);
    cudaGetSymbolAddress((void**)&Bo,  g_Bo);
    cudaGetSymbolAddress((void**)&Obf, g_Obf);

    cudaFuncSetAttribute(attention_tc_kernel,
                         cudaFuncAttributeMaxDynamicSharedMemorySize,
                         ATT_SMEM_BYTES);

    // 0) pack inputs/weights (one launch; y selects tensor)
    dim3 gpack((NTOK * DD + 255) / 256, 7);
    pack_all_kernel<<<gpack, 256>>>(q, k, v, Wq, Wk, Wv, Wo,
                                    Aq, Ak, Av, Bq, Bk, Bv, Bo);

    // 1) projections: [8192,384]bf16 @ [384,2048]bf16 -> fp32
    dim3 gproj(DH / 128, NTOK / 128);
    gemm_bf16_kernel<128,128,32,64,32><<<gproj, 256>>>(Aq, Bq, bq, Qp, NTOK, DH, 3 * DD);
    gemm_bf16_kernel<128,128,32,64,32><<<gproj, 256>>>(Ak, Bk, bk, Kp, NTOK, DH, 3 * DD);
    gemm_bf16_kernel<128,128,32,64,32><<<gproj, 256>>>(Av, Bv, bv, Vp, NTOK, DH, 3 * DD);

    // 2) per-token attention on tensor cores (emits packed bf16 output)
    attention_tc_kernel<<<NTOK, 256, ATT_SMEM_BYTES>>>(Qp, Kp, Vp, Obf);

    // 3) output projection: [8192,6144]bf16 @ [6144,128]bf16 -> fp32
    dim3 gout(DD / 64, NTOK / 64);
    gemm_bf16_kernel<64,64,64,32,16><<<gout, 256>>>(Obf, Bo, bo, out, NTOK, DD, 3 * DH);
}